// round 17
// baseline (speedup 1.0000x reference)
#include <cuda_runtime.h>

#define NQ     1224
#define NSTEPS 50
#define NB     1024
#define NROWS  (NB * (NSTEPS - 1))   // 50176 (b, t) pairs, t in [1, 49]
#define ROWVEC (2 * NQ / 4)          // 612 uint4 in a full 2448-float row
#define NPAIRS (NROWS / 2)           // 25088 row-pairs
#define WARPS_PER_BLOCK 8
#define NBLOCKS (NPAIRS / WARPS_PER_BLOCK)   // 3136, exact

// Allocation-free scratch. g_sum is reset by the last finishing block each
// run (graph replays start clean); the counter self-resets via atomicInc
// wrap semantics.
__device__ double   g_sum = 0.0;
__device__ unsigned g_counter = 0;

// Two (b, t) rows of `batch` per warp, interleaved at 2KB-step granularity.
// Each 2448-wide row is an exact one-hot: a single 1.0f in [0, 2*NQ).
// Per step we issue up to 8 independent 512B warp-loads (4 per active row,
// two adjacent ~9.8KB regions) before any serial ballot dependency -> 2x the
// memory-level parallelism of the single-row version at the SAME per-row 2KB
// overshoot granularity (traffic unchanged). Loaded data is immediately
// collapsed to per-chunk OR words (register pressure); on a hit the owning
// lane re-loads the one identified 512B chunk (guaranteed L1 hit) to locate
// the exact column. The hit's global float index g gives the question
// q = g mod NQ and the label a = (g < NQ); gather pred[b,t-1,q] and
// accumulate the BCE term. pred is in (0,1) by construction, so the
// reference's `p > 0` mask is always satisfied on a hit; an all-zero row
// contributes 0, matching the masked reference.
__global__ __launch_bounds__(256) void dkt_loss_kernel(
    const float* __restrict__ pred,
    const float* __restrict__ batch,
    float* __restrict__ out)
{
    const int pair = blockIdx.x * WARPS_PER_BLOCK + (threadIdx.x >> 5);
    const int lane = threadIdx.x & 31;

    const int rA = 2 * pair;
    const int rB = rA + 1;
    const int bA = rA / (NSTEPS - 1), tA = rA - bA * (NSTEPS - 1) + 1;
    const int bB = rB / (NSTEPS - 1), tB = rB - bB * (NSTEPS - 1) + 1;

    const uint4* rowA = (const uint4*)(batch + ((size_t)bA * NSTEPS + tA) * (size_t)(2 * NQ));
    const uint4* rowB = (const uint4*)(batch + ((size_t)bB * NSTEPS + tB) * (size_t)(2 * NQ));
    const float* predA = pred + ((size_t)bA * NSTEPS + (tA - 1)) * (size_t)NQ;
    const float* predB = pred + ((size_t)bB * NSTEPS + (tB - 1)) * (size_t)NQ;

    bool doneA = false, doneB = false;
    float contrib = 0.0f;

    #pragma unroll 1
    for (int base = 0; base < ROWVEC; base += 128) {
        unsigned oA0 = 0, oA1 = 0, oA2 = 0, oA3 = 0;
        unsigned oB0 = 0, oB1 = 0, oB2 = 0, oB3 = 0;
        const int v0 = base + lane, v1 = v0 + 32, v2 = v0 + 64, v3 = v0 + 96;

        // Up to 8 independent loads issued back-to-back (two 2KB bursts).
        if (!doneA) {
            if (v0 < ROWVEC) { uint4 d = __ldg(rowA + v0); oA0 = d.x | d.y | d.z | d.w; }
            if (v1 < ROWVEC) { uint4 d = __ldg(rowA + v1); oA1 = d.x | d.y | d.z | d.w; }
            if (v2 < ROWVEC) { uint4 d = __ldg(rowA + v2); oA2 = d.x | d.y | d.z | d.w; }
            if (v3 < ROWVEC) { uint4 d = __ldg(rowA + v3); oA3 = d.x | d.y | d.z | d.w; }
        }
        if (!doneB) {
            if (v0 < ROWVEC) { uint4 d = __ldg(rowB + v0); oB0 = d.x | d.y | d.z | d.w; }
            if (v1 < ROWVEC) { uint4 d = __ldg(rowB + v1); oB1 = d.x | d.y | d.z | d.w; }
            if (v2 < ROWVEC) { uint4 d = __ldg(rowB + v2); oB2 = d.x | d.y | d.z | d.w; }
            if (v3 < ROWVEC) { uint4 d = __ldg(rowB + v3); oB3 = d.x | d.y | d.z | d.w; }
        }

        unsigned anyA = oA0 | oA1 | oA2 | oA3;
        unsigned anyB = oB0 | oB1 | oB2 | oB3;
        unsigned mA = __ballot_sync(0xffffffffu, anyA != 0u);
        unsigned mB = __ballot_sync(0xffffffffu, anyB != 0u);

        if (mA) {
            if (anyA) {   // at most one lane warp-wide: the one-hot owner
                int j = oA0 ? 0 : (oA1 ? 1 : (oA2 ? 2 : 3));
                int v = base + lane + 32 * j;
                uint4 d = __ldg(rowA + v);       // L1 hit: just loaded
                int idx = d.x ? 0 : (d.y ? 1 : (d.z ? 2 : 3));
                int g = 4 * v + idx;
                int corr = (g < NQ);
                int q = corr ? g : g - NQ;
                float p = __ldg(predA + q);
                contrib += corr ? logf(p) : logf(1.0f - p);
            }
            doneA = true;   // ballot result is warp-uniform
        }
        if (mB) {
            if (anyB) {
                int j = oB0 ? 0 : (oB1 ? 1 : (oB2 ? 2 : 3));
                int v = base + lane + 32 * j;
                uint4 d = __ldg(rowB + v);
                int idx = d.x ? 0 : (d.y ? 1 : (d.z ? 2 : 3));
                int g = 4 * v + idx;
                int corr = (g < NQ);
                int q = corr ? g : g - NQ;
                float p = __ldg(predB + q);
                contrib += corr ? logf(p) : logf(1.0f - p);
            }
            doneB = true;
        }
        if (doneA && doneB) break;
    }

    // Warp reduction (at most two lanes are nonzero, but reduce anyway).
    #pragma unroll
    for (int o = 16; o; o >>= 1)
        contrib += __shfl_xor_sync(0xffffffffu, contrib, o);

    __shared__ float wsum[WARPS_PER_BLOCK];
    if (lane == 0) wsum[threadIdx.x >> 5] = contrib;
    __syncthreads();

    if (threadIdx.x == 0) {
        float blocksum = 0.0f;
        #pragma unroll
        for (int i = 0; i < WARPS_PER_BLOCK; i++) blocksum += wsum[i];

        // Accumulate in double; overlaps other blocks' scan work.
        atomicAdd(&g_sum, (double)blocksum);
        __threadfence();
        unsigned old = atomicInc(&g_counter, (unsigned)(gridDim.x - 1));
        if (old == gridDim.x - 1) {
            // Last block: all atomicAdds are globally visible (each was
            // fenced before its counter increment). Publish and reset.
            double total = g_sum;
            out[0] = (float)(-total);
            g_sum = 0.0;
        }
    }
}

extern "C" void kernel_launch(void* const* d_in, const int* in_sizes, int n_in,
                              void* d_out, int out_size)
{
    // Identify inputs by element count (robust to metadata ordering):
    // pred  = 1024*50*1224 = 62,668,800
    // batch = 1024*50*2448 = 125,337,600
    const float* pred;
    const float* batch;
    if (in_sizes[0] == NB * NSTEPS * NQ) {
        pred  = (const float*)d_in[0];
        batch = (const float*)d_in[1];
    } else {
        pred  = (const float*)d_in[1];
        batch = (const float*)d_in[0];
    }

    dkt_loss_kernel<<<NBLOCKS, 256>>>(pred, batch, (float*)d_out);
}